// round 14
// baseline (speedup 1.0000x reference)
#include <cuda_runtime.h>
#include <cuda_bf16.h>

// Problem constants (fixed shapes from setup_inputs)
#define B_DIM 8
#define T_DIM 4096
#define D_DIM 1024
#define K_FFT 64
#define F_DIM (K_FFT / 2 + 1)        // 33

// Per-channel time-domain filters, TRANSPOSED layout [dtile][n][dl]:
// g_filt[dt*4096 + n*64 + dl], dt in 0..15, n,dl in 0..63.  256 KB, L2-hot.
__device__ float g_filt[16 * K_FFT * 64];

// ---------------------------------------------------------------------------
// Kernel 1: build all filters once (depend on (d, n) only, not batch).
// Grid 16 blocks (one per 64-channel dtile) x 256 threads.
// Thread: channel ch = tid>>2, 16 n-values (ILP-16 Chebyshev recurrences).
//   filt[d][n] = (mix_w[d]/64) * ( g0 + 2*sum_{f=1..31} g_f cos(pi f n/32)
//                                  + g32 * (-1)^n ),  g = sigmoid(mask[d])
// ---------------------------------------------------------------------------
__global__ void __launch_bounds__(256, 1) spectral_filt_kernel(
    const float* __restrict__ mask, const float* __restrict__ mix_w)
{
    __shared__ float gs_sh[64 * F_DIM];   // weighted sigmoid tile [ch][f]
    __shared__ float tab[K_FFT];          // a[n] = cos(pi n / 32)
    __shared__ float mw_sh[64];

    const int tid = threadIdx.x;
    const int dt  = blockIdx.x;
    const int c0  = dt * 64;

    const float* mrow = mask + (long long)c0 * F_DIM;
    for (int idx = tid; idx < 64 * F_DIM; idx += 256) {
        int f = idx % F_DIM;
        float g = 1.0f / (1.0f + __expf(-mrow[idx]));
        gs_sh[idx] = (f == 0 || f == 32) ? g : (2.0f * g);
    }
    if (tid < K_FFT)
        tab[tid] = cospif((float)tid * (1.0f / 32.0f));   // exact twiddles
    if (tid < 64)
        mw_sh[tid] = mix_w[c0 + tid] * (1.0f / 64.0f);
    __syncthreads();

    const int ch = tid >> 2;              // 0..63
    const int n0 = (tid & 3) * 16;        // 16 consecutive n-values
    const float* gd = gs_sh + ch * F_DIM;

    float a2[16], cc[16], cp[16], s[16];
    const float g0 = gd[0];
    #pragma unroll
    for (int i = 0; i < 16; i++) {
        float a = tab[n0 + i];
        a2[i] = a + a; cp[i] = 1.0f; cc[i] = a; s[i] = g0;
    }
    #pragma unroll
    for (int f = 1; f < 32; f++) {
        const float gf = gd[f];
        #pragma unroll
        for (int i = 0; i < 16; i++) {
            s[i] = fmaf(gf, cc[i], s[i]);
            float cn = fmaf(a2[i], cc[i], -cp[i]);
            cp[i] = cc[i]; cc[i] = cn;
        }
    }
    const float g32 = gd[32];
    const float mw  = mw_sh[ch];
    float* fbase = g_filt + dt * (K_FFT * 64);
    #pragma unroll
    for (int i = 0; i < 16; i++)
        fbase[(n0 + i) * 64 + ch] = fmaf(g32, cc[i], s[i]) * mw;   // [n][dl]
}

// ---------------------------------------------------------------------------
// Kernel 2: circular convolution, build-free.
// Grid 256 = (b:8) x (dtile:16) x (th:2 time-halves); block 256 threads.
// Thread owns (channel dl, 8 timesteps). f staged as identity float4 copy
// (transposed layout), fr[64] register rotation -> pure compile-time FFMA.
// ---------------------------------------------------------------------------
__global__ void __launch_bounds__(256, 2) spectral_conv_kernel(
    const float* __restrict__ x, float* __restrict__ out)
{
    __shared__ float w_sh[K_FFT * 64];    // window [k][dl]
    __shared__ float f_sh[K_FFT * 64];    // filter [n][dl] (conflict-free reads)

    const int bid = blockIdx.x;
    const int tid = threadIdx.x;

    const int b  = bid >> 5;              // 0..7
    const int dt = (bid >> 1) & 15;       // 0..15
    const int th = bid & 1;               // time half
    const int d0 = dt * 64;

    // Stage window + filter, fully float4-vectorized (identity copies).
    const float4* xb4 = (const float4*)(x + ((long long)b * T_DIM + (T_DIM - K_FFT)) * D_DIM + d0);
    const float4* fg4 = (const float4*)(g_filt + dt * (K_FFT * 64));
    float4* w4 = (float4*)w_sh;
    float4* f4 = (float4*)f_sh;
    #pragma unroll
    for (int i = 0; i < 4; i++) {
        int idx4 = tid + i * 256;         // 0..1023
        int k = idx4 >> 4, c4 = idx4 & 15;
        w4[idx4] = xb4[k * (D_DIM / 4) + c4];
        f4[idx4] = fg4[idx4];
    }
    __syncthreads();

    const int dl = tid & 63;
    const int t0 = th * 32 + (tid >> 6) * 8;   // 8 outputs per thread

    // Pre-rotated filter in registers: fr[i] = f[(t0+i)&63][dl]
    //   -> y[t0+j] = sum_k w[k] * fr[(j-k)&63], compile-time reg indices.
    float fr[K_FFT];
    #pragma unroll
    for (int i = 0; i < K_FFT; i++)
        fr[i] = f_sh[((t0 + i) & 63) * 64 + dl];

    float acc[8];
    #pragma unroll
    for (int j = 0; j < 8; j++) acc[j] = 0.0f;

    #pragma unroll
    for (int kc = 0; kc < K_FFT; kc += 8) {
        float wbuf[8];
        #pragma unroll
        for (int u = 0; u < 8; u++)
            wbuf[u] = w_sh[(kc + u) * 64 + dl];
        #pragma unroll
        for (int u = 0; u < 8; u++) {
            const int k = kc + u;
            #pragma unroll
            for (int j = 0; j < 8; j++)
                acc[j] += wbuf[u] * fr[(j - k + K_FFT) & 63];
        }
    }

    float* ob = out + ((long long)b * T_DIM + (T_DIM - K_FFT)) * D_DIM + d0;
    #pragma unroll
    for (int j = 0; j < 8; j++)
        ob[(long long)(t0 + j) * D_DIM + dl] = acc[j];
}

// ---------------------------------------------------------------------------
// Launch: memset node (~6.6 TB/s driver fill) -> filt -> conv.
// ---------------------------------------------------------------------------
extern "C" void kernel_launch(void* const* d_in, const int* in_sizes, int n_in,
                              void* d_out, int out_size)
{
    const float* x     = (const float*)d_in[0];   // (B, T, D) fp32
    const float* mask  = (const float*)d_in[1];   // (D, 33)   fp32
    const float* mix_w = (const float*)d_in[2];   // (D,)      fp32
    float* out = (float*)d_out;                   // (B, T, D) fp32

    cudaMemsetAsync(out, 0, (size_t)out_size * sizeof(float), 0);
    spectral_filt_kernel<<<16, 256>>>(mask, mix_w);
    spectral_conv_kernel<<<256, 256>>>(x, out);
}

// round 15
// speedup vs baseline: 1.0587x; 1.0587x over previous
#include <cuda_runtime.h>
#include <cuda_bf16.h>

// Problem constants (fixed shapes from setup_inputs)
#define B_DIM 8
#define T_DIM 4096
#define D_DIM 1024
#define K_FFT 64
#define F_DIM (K_FFT / 2 + 1)        // 33

#define MSET_BATCHES 5               // batches fully zeroed by the driver memset
#define NUM_CONV 256                 // (b:8) x (dtile:16) x (th:2)
#define GRID_TOTAL 444               // 3 blocks/SM x 148 SMs: one exact wave
#define NUM_FILL (GRID_TOTAL - NUM_CONV)   // 188

// Fill region: batches MSET_BATCHES..7, rows [0, T-K), as float4.
#define Z4_PER_B   ((T_DIM - K_FFT) * D_DIM / 4)          // 1,032,192
#define FILL_B     (B_DIM - MSET_BATCHES)                  // 3
#define FILL4      (Z4_PER_B * FILL_B)                     // 3,096,576
#define BSTRIDE4   (T_DIM * D_DIM / 4)                     // 4,194,304

// Per-channel time-domain filters, transposed layout [dtile][n][dl] (256 KB).
__device__ float g_filt[16 * K_FFT * 64];

// ---------------------------------------------------------------------------
// Kernel 1: build all filters once.  filt[d][n] = (mix_w[d]/64) *
//   ( g0 + 2*sum_{f=1..31} g_f cos(pi f n/32) + g32 * (-1)^n ), g=sigmoid(mask)
// Grid 16 x 256; thread = (channel, 16 n-values), ILP-16 Chebyshev.
// ---------------------------------------------------------------------------
__global__ void __launch_bounds__(256, 1) spectral_filt_kernel(
    const float* __restrict__ mask, const float* __restrict__ mix_w)
{
    __shared__ float gs_sh[64 * F_DIM];
    __shared__ float tab[K_FFT];
    __shared__ float mw_sh[64];

    const int tid = threadIdx.x;
    const int dt  = blockIdx.x;
    const int c0  = dt * 64;

    const float* mrow = mask + (long long)c0 * F_DIM;
    for (int idx = tid; idx < 64 * F_DIM; idx += 256) {
        int f = idx % F_DIM;
        float g = 1.0f / (1.0f + __expf(-mrow[idx]));
        gs_sh[idx] = (f == 0 || f == 32) ? g : (2.0f * g);
    }
    if (tid < K_FFT)
        tab[tid] = cospif((float)tid * (1.0f / 32.0f));   // exact twiddles
    if (tid < 64)
        mw_sh[tid] = mix_w[c0 + tid] * (1.0f / 64.0f);
    __syncthreads();

    const int ch = tid >> 2;
    const int n0 = (tid & 3) * 16;
    const float* gd = gs_sh + ch * F_DIM;

    float a2[16], cc[16], cp[16], s[16];
    const float g0 = gd[0];
    #pragma unroll
    for (int i = 0; i < 16; i++) {
        float a = tab[n0 + i];
        a2[i] = a + a; cp[i] = 1.0f; cc[i] = a; s[i] = g0;
    }
    #pragma unroll
    for (int f = 1; f < 32; f++) {
        const float gf = gd[f];
        #pragma unroll
        for (int i = 0; i < 16; i++) {
            s[i] = fmaf(gf, cc[i], s[i]);
            float cn = fmaf(a2[i], cc[i], -cp[i]);
            cp[i] = cc[i]; cc[i] = cn;
        }
    }
    const float g32 = gd[32];
    const float mw  = mw_sh[ch];
    float* fbase = g_filt + dt * (K_FFT * 64);
    #pragma unroll
    for (int i = 0; i < 16; i++)
        fbase[(n0 + i) * 64 + ch] = fmaf(g32, cc[i], s[i]) * mw;   // [n][dl]
}

// ---------------------------------------------------------------------------
// Kernel 2 (fused): blocks [0,256) = conv (all 8 batches' windows, build-free,
// R14 fast path); blocks [256,444) = STG zero-fill of batches 5..7's zero rows.
// Conv hides under the fill; regions are disjoint.
// ---------------------------------------------------------------------------
__global__ void __launch_bounds__(256, 3) spectral_fused_kernel(
    const float* __restrict__ x, float* __restrict__ out)
{
    __shared__ float w_sh[K_FFT * 64];    // window [k][dl]
    __shared__ float f_sh[K_FFT * 64];    // filter [n][dl]

    const int bid = blockIdx.x;
    const int tid = threadIdx.x;

    if (bid >= NUM_CONV) {
        // ---- fill path: zero rows [0, T-K) of batches 5..7 ----
        const float4 z = make_float4(0.f, 0.f, 0.f, 0.f);
        float4* __restrict__ o4 = (float4*)out;
        const int stride = NUM_FILL * 256;                 // 48,128
        for (int i = (bid - NUM_CONV) * 256 + tid; i < FILL4; i += stride) {
            int rb  = i / Z4_PER_B;                        // 0..2 (const-div)
            int off = i - rb * Z4_PER_B;
            __stcs(&o4[(MSET_BATCHES + rb) * BSTRIDE4 + off], z);
        }
        return;
    }

    // ---- conv path ----
    const int b  = bid >> 5;              // 0..7
    const int dt = (bid >> 1) & 15;       // 0..15
    const int th = bid & 1;               // time half
    const int d0 = dt * 64;

    // Stage window + filter, float4-vectorized identity copies.
    const float4* xb4 = (const float4*)(x + ((long long)b * T_DIM + (T_DIM - K_FFT)) * D_DIM + d0);
    const float4* fg4 = (const float4*)(g_filt + dt * (K_FFT * 64));
    float4* w4 = (float4*)w_sh;
    float4* f4 = (float4*)f_sh;
    #pragma unroll
    for (int i = 0; i < 4; i++) {
        int idx4 = tid + i * 256;         // 0..1023
        int k = idx4 >> 4, c4 = idx4 & 15;
        w4[idx4] = xb4[k * (D_DIM / 4) + c4];
        f4[idx4] = fg4[idx4];
    }
    __syncthreads();

    const int dl = tid & 63;
    const int t0 = th * 32 + (tid >> 6) * 8;   // 8 outputs per thread

    // Pre-rotated filter in registers: fr[i] = f[(t0+i)&63][dl]
    float fr[K_FFT];
    #pragma unroll
    for (int i = 0; i < K_FFT; i++)
        fr[i] = f_sh[((t0 + i) & 63) * 64 + dl];

    float acc[8];
    #pragma unroll
    for (int j = 0; j < 8; j++) acc[j] = 0.0f;

    #pragma unroll
    for (int kc = 0; kc < K_FFT; kc += 8) {
        float wbuf[8];
        #pragma unroll
        for (int u = 0; u < 8; u++)
            wbuf[u] = w_sh[(kc + u) * 64 + dl];
        #pragma unroll
        for (int u = 0; u < 8; u++) {
            const int k = kc + u;
            #pragma unroll
            for (int j = 0; j < 8; j++)
                acc[j] += wbuf[u] * fr[(j - k + K_FFT) & 63];
        }
    }

    float* ob = out + ((long long)b * T_DIM + (T_DIM - K_FFT)) * D_DIM + d0;
    #pragma unroll
    for (int j = 0; j < 8; j++)
        ob[(long long)(t0 + j) * D_DIM + dl] = acc[j];
}

// ---------------------------------------------------------------------------
// Launch: prefix memset (batches 0..4, driver fill ~6.6 TB/s) -> filt ->
// fused conv+fill. Conv overwrites the memset's window rows (stream-ordered).
// ---------------------------------------------------------------------------
extern "C" void kernel_launch(void* const* d_in, const int* in_sizes, int n_in,
                              void* d_out, int out_size)
{
    const float* x     = (const float*)d_in[0];   // (B, T, D) fp32
    const float* mask  = (const float*)d_in[1];   // (D, 33)   fp32
    const float* mix_w = (const float*)d_in[2];   // (D,)      fp32
    float* out = (float*)d_out;                   // (B, T, D) fp32

    const size_t mset_bytes = (size_t)MSET_BATCHES * T_DIM * D_DIM * sizeof(float);
    cudaMemsetAsync(out, 0, mset_bytes, 0);
    spectral_filt_kernel<<<16, 256>>>(mask, mix_w);
    spectral_fused_kernel<<<GRID_TOTAL, 256>>>(x, out);
}

// round 16
// speedup vs baseline: 1.2008x; 1.1342x over previous
#include <cuda_runtime.h>
#include <cuda_bf16.h>

// Problem constants (fixed shapes from setup_inputs)
#define B_DIM 8
#define T_DIM 4096
#define D_DIM 1024
#define K_FFT 64
#define F_DIM (K_FFT / 2 + 1)        // 33

#define MSET_BATCHES 5               // batches fully zeroed by the driver memset
#define GRID_BLOCKS  148             // one block per SM
#define NTHREADS     512
#define NUM_CONV_BLK 128             // blocks whose upper half does conv: (b:8)x(dt:16)

// Fill region: batches 5..7, rows [0, T-K), as float4.
#define Z4_PER_B   ((T_DIM - K_FFT) * D_DIM / 4)   // 1,032,192
#define FILL4      (Z4_PER_B * 3)                  // 3,096,576
#define BSTRIDE4   (T_DIM * D_DIM / 4)             // 4,194,304
// Fill threads: lower halves of all 148 blocks + upper halves of blocks 128..147
#define NFILL_LO   (GRID_BLOCKS * 256)             // 37,888
#define NFILL_TOT  (NFILL_LO + (GRID_BLOCKS - NUM_CONV_BLK) * 256)  // 43,008
// 3,096,576 / 43,008 = 72 iterations exactly.

// ---------------------------------------------------------------------------
// Warp-specialized fused kernel (one block per SM):
//   threads [0,256):   zero-fill batches 5..7 (all blocks)
//   threads [256,512): blocks < 128: filter build + conv for one (b, dtile);
//                      blocks >= 128: extra fill threads.
// Conv half syncs only among itself via named barrier (bar.sync 1, 256), so
// fill warps stream stores uninterrupted while conv FFMA fills idle issue slots.
// ---------------------------------------------------------------------------
__global__ void __launch_bounds__(NTHREADS, 1) spectral_fused_kernel(
    const float* __restrict__ x, const float* __restrict__ mask,
    const float* __restrict__ mix_w, float* __restrict__ out)
{
    __shared__ float gs_sh[64 * F_DIM];   // weighted sigmoid(mask) [ch][f]
    __shared__ float tab[K_FFT];          // a[n] = cos(pi n / 32)
    __shared__ float mw_sh[64];           // mix_w/64
    __shared__ float w_sh[K_FFT * 64];    // window [k][dl]
    __shared__ float f_sh[K_FFT * 64];    // filter [n][dl]

    const int bid = blockIdx.x;
    const int tid = threadIdx.x;

    // ---------------- fill path ----------------
    if (tid < 256 || bid >= NUM_CONV_BLK) {
        int ftid = (tid < 256) ? (bid * 256 + tid)
                               : (NFILL_LO + (bid - NUM_CONV_BLK) * 256 + (tid - 256));
        const float4 z = make_float4(0.f, 0.f, 0.f, 0.f);
        float4* __restrict__ o4 = (float4*)out;
        #pragma unroll 4
        for (int i = ftid; i < FILL4; i += NFILL_TOT) {
            int rb  = i / Z4_PER_B;                    // 0..2 (const-div -> mulhi)
            int off = i - rb * Z4_PER_B;
            __stcs(&o4[(MSET_BATCHES + rb) * BSTRIDE4 + off], z);
        }
        return;
    }

    // ---------------- conv path: threads 256..511 of blocks 0..127 ----------------
    const int wg  = tid - 256;            // 0..255
    const int b   = bid >> 4;             // 0..7
    const int dt  = bid & 15;             // 0..15
    const int d0  = dt * 64;

    // Stage weighted sigmoid(mask), twiddles, mix_w, and the window (float4).
    const float* mrow = mask + (long long)d0 * F_DIM;
    for (int idx = wg; idx < 64 * F_DIM; idx += 256) {
        int f = idx % F_DIM;
        float g = 1.0f / (1.0f + __expf(-mrow[idx]));
        gs_sh[idx] = (f == 0 || f == 32) ? g : (2.0f * g);
    }
    if (wg < K_FFT)
        tab[wg] = cospif((float)wg * (1.0f / 32.0f));   // exact twiddles
    if (wg < 64)
        mw_sh[wg] = mix_w[d0 + wg] * (1.0f / 64.0f);

    const float4* xb4 = (const float4*)(x + ((long long)b * T_DIM + (T_DIM - K_FFT)) * D_DIM + d0);
    float4* w4 = (float4*)w_sh;
    #pragma unroll
    for (int i = 0; i < 4; i++) {
        int idx4 = wg + i * 256;          // 0..1023
        int k = idx4 >> 4, c4 = idx4 & 15;
        w4[idx4] = xb4[k * (D_DIM / 4) + c4];
    }
    asm volatile("bar.sync 1, 256;" ::: "memory");

    // Filter build: thread = (channel ch, 16 n-values), ILP-16 Chebyshev.
    //   f[n][ch] = (mix_w/64)*( g0 + sum_{f=1..31} 2 g_f cos(pi f n/32) + g32 (-1)^n )
    {
        const int ch = wg >> 2;           // 0..63
        const int n0 = (wg & 3) * 16;     // 16 consecutive n
        const float* gd = gs_sh + ch * F_DIM;

        float a2[16], cc[16], cp[16], s[16];
        const float g0 = gd[0];
        #pragma unroll
        for (int i = 0; i < 16; i++) {
            float a = tab[n0 + i];
            a2[i] = a + a; cp[i] = 1.0f; cc[i] = a; s[i] = g0;
        }
        #pragma unroll
        for (int f = 1; f < 32; f++) {
            const float gf = gd[f];       // one LDS feeds 16 FMA chains
            #pragma unroll
            for (int i = 0; i < 16; i++) {
                s[i] = fmaf(gf, cc[i], s[i]);
                float cn = fmaf(a2[i], cc[i], -cp[i]);
                cp[i] = cc[i]; cc[i] = cn;
            }
        }
        const float g32 = gd[32];
        const float mw  = mw_sh[ch];
        #pragma unroll
        for (int i = 0; i < 16; i++)
            f_sh[(n0 + i) * 64 + ch] = fmaf(g32, cc[i], s[i]) * mw;
    }
    asm volatile("bar.sync 1, 256;" ::: "memory");

    // Circular convolution: thread = (channel dl, 16 timesteps).
    const int dl = wg & 63;
    const int t0 = (wg >> 6) * 16;

    float fr[K_FFT];                      // pre-rotated filter in registers
    #pragma unroll
    for (int i = 0; i < K_FFT; i++)
        fr[i] = f_sh[((t0 + i) & 63) * 64 + dl];

    float acc[16];
    #pragma unroll
    for (int j = 0; j < 16; j++) acc[j] = 0.0f;

    #pragma unroll
    for (int kc = 0; kc < K_FFT; kc += 8) {
        float wbuf[8];
        #pragma unroll
        for (int u = 0; u < 8; u++)
            wbuf[u] = w_sh[(kc + u) * 64 + dl];
        #pragma unroll
        for (int u = 0; u < 8; u++) {
            const int k = kc + u;
            #pragma unroll
            for (int j = 0; j < 16; j++)
                acc[j] += wbuf[u] * fr[(j - k + K_FFT) & 63];   // compile-time idx
        }
    }

    float* ob = out + ((long long)b * T_DIM + (T_DIM - K_FFT)) * D_DIM + d0;
    #pragma unroll
    for (int j = 0; j < 16; j++)
        ob[(long long)(t0 + j) * D_DIM + dl] = acc[j];
}

// ---------------------------------------------------------------------------
// Launch: memset of batches 0..4 (driver fill ~6.9 TB/s) -> fused kernel
// (fills batches 5..7's zero rows + all windows). Two graph nodes.
// ---------------------------------------------------------------------------
extern "C" void kernel_launch(void* const* d_in, const int* in_sizes, int n_in,
                              void* d_out, int out_size)
{
    const float* x     = (const float*)d_in[0];   // (B, T, D) fp32
    const float* mask  = (const float*)d_in[1];   // (D, 33)   fp32
    const float* mix_w = (const float*)d_in[2];   // (D,)      fp32
    float* out = (float*)d_out;                   // (B, T, D) fp32

    const size_t mset_bytes = (size_t)MSET_BATCHES * T_DIM * D_DIM * sizeof(float);
    cudaMemsetAsync(out, 0, mset_bytes, 0);
    spectral_fused_kernel<<<GRID_BLOCKS, NTHREADS>>>(x, mask, mix_w, out);
}